// round 11
// baseline (speedup 1.0000x reference)
#include <cuda_runtime.h>
#include <math.h>

#define BATCH 256
#define NN    1024
#define PP    128
#define DIN   784
#define COUT  10
#define CH    32                     /* columns per CTA */
#define NEV   64                     /* RK4 evals */
#define NGRP  8                      /* row groups (blockIdx.y) */
#define GXS   32                     /* CTAs per group (blockIdx.x) */

#define TWO_PI_F 6.283185307179586f
#define DT       0.03125f            /* T/N_STEPS = 0.5/16, exact in fp32 */
#define BETA_N   (2.0f/1024.0f)
#define A_ANC    0.08f
#define OME      (TWO_PI_F*200.0f)

typedef unsigned long long ull;

__device__ __forceinline__ ull pack2(float a, float b) {
    ull r; asm("mov.b64 %0,{%1,%2};" : "=l"(r) : "f"(a), "f"(b)); return r;
}
__device__ __forceinline__ ull fma2(ull a, ull b, ull c) {
    ull d; asm("fma.rn.f32x2 %0,%1,%2,%3;" : "=l"(d) : "l"(a), "l"(b), "l"(c));
    return d;
}
__device__ __forceinline__ float hadd2(ull a) {
    float lo, hi;
    asm("mov.b64 {%0,%1},%2;" : "=f"(lo), "=f"(hi) : "l"(a));
    return lo + hi;
}
__device__ __forceinline__ unsigned su32(const void* p) {
    return (unsigned)__cvta_generic_to_shared(p);
}
#define CP16(dst, src) \
    asm volatile("cp.async.cg.shared.global [%0], [%1], 16;" :: "r"(dst), "l"(src))
#define CP_COMMIT() asm volatile("cp.async.commit_group;")
#define CP_WAIT(n)  asm volatile("cp.async.wait_group %0;" :: "n"(n))

struct EvalConsts { float sA[NEV]; float cA[NEV]; float cN[NEV]; };

/* ---- device scratch (static globals; no allocation allowed) ---- */
__device__ float g_xc[PP*NN];       /* cos(xi) [p][n] */
__device__ float g_xs[PP*NN];       /* sin(xi) [p][n] */
__device__ float g_phi[BATCH*NN];   /* base state */
__device__ float g_fc[BATCH*NN];    /* cos(phi_eval) features (encoder out) */
__device__ float g_fs[BATCH*NN];    /* sin(phi_eval) features */
__device__ float g_m[3][BATCH*PP];  /* rotating overlap buffers */
__device__ unsigned g_cnt[NGRP*NEV]; /* per-(group,eval) barrier counters */

/* ---- shared layout (floats) ---- */
#define SW_STRIDE 130                /* w tile [32][130] */
#define SX_STRIDE 36                 /* xc/xs tiles [128][36] */
#define SC_STRIDE 36                 /* c/s/phi/acc tiles [32][36] */
#define SR_STRIDE 36                 /* reduction: 256 writers x 36 */
#define SW_FLOATS (32*SW_STRIDE)     /* 4160 */
#define SX_FLOATS (128*SX_STRIDE)    /* 4608 */
#define SC_FLOATS (32*SC_STRIDE)     /* 1152 */
#define SR_FLOATS (256*SR_STRIDE)    /* 9216; first 4096 alias m-prefetch */
#define SMEM_FLOATS (SW_FLOATS + 2*SX_FLOATS + 4*SC_FLOATS + SR_FLOATS)
#define SMEM_BYTES  (SMEM_FLOATS*4)  /* 108800 bytes -> 2 CTAs/SM */

/* ================= init: cos/sin of xi, zero m bufs + barrier cnt ======= */
__global__ void k_init(const float* __restrict__ xi) {
    int i = blockIdx.x*256 + threadIdx.x;
    if (i < PP*NN) {
        float v = xi[i];
        g_xc[i] = cosf(v);
        g_xs[i] = sinf(v);
    }
    if (i < BATCH*PP) { g_m[0][i] = 0.f; g_m[1][i] = 0.f; }
    if (i < NGRP*NEV) g_cnt[i] = 0u;
}

/* load xc/xs tiles [128 p][32 n] for column chunk n0 (LDG path, encoder) */
__device__ __forceinline__ void load_xtiles(float* sXC, float* sXS, int n0) {
    for (int i = threadIdx.x; i < 128*8; i += 256) {
        int p = i >> 3, q = (i & 7) << 2;
        float4 a = *(const float4*)&g_xc[p*NN + n0 + q];
        *(float4*)&sXC[p*SX_STRIDE + q] = a;
        float4 b = *(const float4*)&g_xs[p*NN + n0 + q];
        *(float4*)&sXS[p*SX_STRIDE + q] = b;
    }
}

/* partial m over this CTA's 32-col chunk, atomicAdd into mbuf.
   Packed f32x2 over n: acc[pp][r] = (sum of n-pair lo, sum of n-pair hi).
   Tile: 8 rows x 4 patterns per thread-pair, n split in 2 halves of 16;
   halves combined via shfl_xor(16); ns==0 lanes issue the atomics. */
__device__ __forceinline__ void m_tail(const float* sC, const float* sS,
                                       const float* sXC, const float* sXS,
                                       float* mbuf, int r0) {
    int t = threadIdx.x;
    int w = t >> 5, l = t & 31;
    int ns   = l >> 4;               /* n half: 0/1 */
    int tile = w*16 + (l & 15);      /* 0..127 */
    int rowg = tile >> 5;            /* 0..3  -> rows rowg*8.. */
    int pg   = tile & 31;            /* 0..31 -> pats pg + 32*pp */
    ull acc[32];
#pragma unroll
    for (int i = 0; i < 32; i++) acc[i] = 0ull;
    const float* cB  = sC  + (rowg*8)*SC_STRIDE + ns*16;
    const float* sB  = sS  + (rowg*8)*SC_STRIDE + ns*16;
    const float* xcB = sXC + pg*SX_STRIDE + ns*16;
    const float* xsB = sXS + pg*SX_STRIDE + ns*16;
#pragma unroll
    for (int nn = 0; nn < 16; nn += 4) {
        ulonglong2 cr[8], sr[8];
#pragma unroll
        for (int r = 0; r < 8; r++) {
            cr[r] = *(const ulonglong2*)&cB[r*SC_STRIDE + nn];
            sr[r] = *(const ulonglong2*)&sB[r*SC_STRIDE + nn];
        }
#pragma unroll
        for (int pp = 0; pp < 4; pp++) {
            ulonglong2 xc2 = *(const ulonglong2*)&xcB[pp*32*SX_STRIDE + nn];
            ulonglong2 xs2 = *(const ulonglong2*)&xsB[pp*32*SX_STRIDE + nn];
#pragma unroll
            for (int r = 0; r < 8; r++) {
                ull a = acc[pp*8 + r];
                a = fma2(cr[r].x, xc2.x, a);
                a = fma2(cr[r].y, xc2.y, a);
                a = fma2(sr[r].x, xs2.x, a);
                a = fma2(sr[r].y, xs2.y, a);
                acc[pp*8 + r] = a;
            }
        }
    }
#pragma unroll
    for (int pp = 0; pp < 4; pp++)
#pragma unroll
        for (int r = 0; r < 8; r++) {
            float v = hadd2(acc[pp*8 + r]);
            v += __shfl_xor_sync(0xffffffffu, v, 16);
            if (ns == 0)
                atomicAdd(&mbuf[(r0 + rowg*8 + r)*PP + pg + 32*pp], v);
        }
}

/* ================= encoder: phi0 = 2pi*sigmoid(x @ Wenc^T + b), + m0 ====
   Software-pipelined: LDG chunk i+1 -> compute chunk i -> STS -> 1 sync. */
__global__ void __launch_bounds__(256, 2)
k_encoder(const float* __restrict__ x,
          const float* __restrict__ Wenc,
          const float* __restrict__ benc) {
    extern __shared__ float sm[];
    /* double-buffered staging inside sW region: 4 x 544 = 2176 floats */
    float* sA0 = sm;
    float* sA1 = sm + 544;
    float* sB0 = sm + 1088;
    float* sB1 = sm + 1632;
    float* sXC = sm + SW_FLOATS;
    float* sXS = sXC + SX_FLOATS;
    float* sC  = sXS + SX_FLOATS;
    float* sS  = sC + SC_FLOATS;

    int n0 = blockIdx.x*CH, r0 = blockIdx.y*32;
    int tid = threadIdx.x;
    int row = tid >> 3, ng = tid & 7, nb = ng*4;

    float acc[4];
#pragma unroll
    for (int i = 0; i < 4; i++) acc[i] = 0.f;

    /* preload chunk 0 */
#pragma unroll
    for (int it = 0; it < 2; it++) {
        int i = tid + it*256;
        int r = i >> 4, j = i & 15;
        sA0[r*17 + j] = x[(r0+r)*DIN + j];
        sB0[r*17 + j] = Wenc[(n0+r)*DIN + j];
    }
    __syncthreads();

    for (int ch = 0; ch < 49; ch++) {
        const float* sAc = (ch & 1) ? sA1 : sA0;
        const float* sBc = (ch & 1) ? sB1 : sB0;
        float* sAn = (ch & 1) ? sA0 : sA1;
        float* sBn = (ch & 1) ? sB0 : sB1;

        float aN[2], bN[2];
        if (ch < 48) {
            int d1 = (ch + 1)*16;
#pragma unroll
            for (int it = 0; it < 2; it++) {
                int i = tid + it*256;
                int r = i >> 4, j = i & 15;
                aN[it] = x[(r0+r)*DIN + d1 + j];
                bN[it] = Wenc[(n0+r)*DIN + d1 + j];
            }
        }
#pragma unroll
        for (int j = 0; j < 16; j++) {
            float xa = sAc[row*17 + j];
#pragma unroll
            for (int i = 0; i < 4; i++) acc[i] += xa * sBc[(nb+i)*17 + j];
        }
        if (ch < 48) {
#pragma unroll
            for (int it = 0; it < 2; it++) {
                int i = tid + it*256;
                int r = i >> 4, j = i & 15;
                sAn[r*17 + j] = aN[it];
                sBn[r*17 + j] = bN[it];
            }
        }
        __syncthreads();
    }

    load_xtiles(sXC, sXS, n0);

#pragma unroll
    for (int i = 0; i < 4; i++) {
        float z  = acc[i] + benc[n0 + nb + i];
        float p0 = TWO_PI_F / (1.0f + expf(-z));
        int gi = (r0+row)*NN + n0 + nb + i;
        g_phi[gi]  = p0;
        float ss, cc;
        __sincosf(p0, &ss, &cc);
        g_fc[gi] = cc;
        g_fs[gi] = ss;
        sC[row*SC_STRIDE + nb + i] = cc;
        sS[row*SC_STRIDE + nb + i] = ss;
    }
    __syncthreads();
    m_tail(sC, sS, sXC, sXS, g_m[0], r0);
}

/* ================= persistent RK4 kernel: all 64 evals =================== */
__global__ void __launch_bounds__(256, 2)
k_run(EvalConsts ec) {
    extern __shared__ float sm[];
    float* sW  = sm;
    float* sXC = sm + SW_FLOATS;
    float* sXS = sXC + SX_FLOATS;
    float* sC  = sXS + SX_FLOATS;      /* cos features of eval point */
    float* sS  = sC + SC_FLOATS;       /* sin features of eval point */
    float* sP  = sS + SC_FLOATS;       /* base phi                   */
    float* sA  = sP + SC_FLOATS;       /* RK4 accumulator            */
    float* sR  = sA + SC_FLOATS;       /* GEMM partials; [0,4096)=m  */

    int n0 = blockIdx.x*CH, r0 = blockIdx.y*32;
    int tid = threadIdx.x;
    int row = tid >> 3, cf = tid & 7;
    int so  = row*SC_STRIDE + cf*4;
    int gso = (r0+row)*NN + n0 + cf*4;
    int cta = blockIdx.y*GXS + blockIdx.x;
    int grp = blockIdx.y;

    /* ---- one-time loads: xi tiles + state ---- */
#pragma unroll
    for (int it = 0; it < 4; it++) {
        int i = tid + it*256;
        int p = i >> 3, q = (i & 7) << 2;
        CP16(su32(&sXC[p*SX_STRIDE + q]), &g_xc[p*NN + n0 + q]);
        CP16(su32(&sXS[p*SX_STRIDE + q]), &g_xs[p*NN + n0 + q]);
    }
    CP16(su32(&sC[so]), &g_fc[gso]);
    CP16(su32(&sS[so]), &g_fs[gso]);
    CP16(su32(&sP[so]), &g_phi[gso]);
    CP_COMMIT();

    for (int e = 0; e < NEV; e++) {
        int sub  = e & 3;
        int bufR = e % 3, bufW = (e + 1) % 3, bufZ = (e + 2) % 3;
        float sAnc = ec.sA[e], cAnc = ec.cA[e], cNext = ec.cN[e];

        /* prefetch m slice for this eval */
        {
            const float* gmp = &g_m[bufR][(r0+row)*PP + cf*16];
            unsigned d = su32(&sR[row*PP + cf*16]);
            CP16(d,      gmp);
            CP16(d + 16, gmp + 4);
            CP16(d + 32, gmp + 8);
            CP16(d + 48, gmp + 12);
        }
        CP_COMMIT();

        /* zero this group's slice of the buffer used two evals ahead */
        if (tid < 128) g_m[bufZ][cta*128 + tid] = 0.f;

        CP_WAIT(0);
        /* ---- softmax over 128 patterns (arg in [-2,2]: no max shift) ---- */
        {
            const float* mrow = &sR[row*PP + cf*16];
            float a[16];
            float ssum = 0.f;
#pragma unroll
            for (int j = 0; j < 16; j++) {
                a[j] = __expf(mrow[j] * BETA_N);
                ssum += a[j];
            }
#pragma unroll
            for (int w = 1; w < 8; w <<= 1)
                ssum += __shfl_xor_sync(0xffffffffu, ssum, w);
            float inv = 1.0f / ssum;
#pragma unroll
            for (int j = 0; j < 16; j++)
                sW[row*SW_STRIDE + cf*16 + j] = a[j] * inv;
        }
        __syncthreads();

        /* ---- coupling GEMM, tile 4 rows x 4 cols (f32x2), K-split 4 ---- */
        {
            int ks   = tid >> 6;
            int r6   = tid & 63;
            int rowg = r6 >> 3;
            int colg = r6 & 7;
            ull aC0[4], aC1[4], aS0[4], aS1[4];
#pragma unroll
            for (int i = 0; i < 4; i++) { aC0[i]=0ull; aC1[i]=0ull; aS0[i]=0ull; aS1[i]=0ull; }
            const float* wB  = &sW[(rowg*4)*SW_STRIDE + ks*32];
            const float* xcB = &sXC[(ks*32)*SX_STRIDE + colg*4];
            const float* xsB = &sXS[(ks*32)*SX_STRIDE + colg*4];
#pragma unroll 4
            for (int p = 0; p < 32; p++) {
                ulonglong2 cp = *(const ulonglong2*)&xcB[p*SX_STRIDE];
                ulonglong2 spv = *(const ulonglong2*)&xsB[p*SX_STRIDE];
#pragma unroll
                for (int i = 0; i < 4; i++) {
                    float wv = wB[i*SW_STRIDE + p];
                    ull wp = pack2(wv, wv);
                    aC0[i] = fma2(wp, cp.x,  aC0[i]);
                    aC1[i] = fma2(wp, cp.y,  aC1[i]);
                    aS0[i] = fma2(wp, spv.x, aS0[i]);
                    aS1[i] = fma2(wp, spv.y, aS1[i]);
                }
            }
            float* rr = &sR[tid*SR_STRIDE];
#pragma unroll
            for (int i = 0; i < 4; i++) {
                *(ull*)&rr[i*4]        = aC0[i];
                *(ull*)&rr[i*4 + 2]    = aC1[i];
                *(ull*)&rr[16 + i*4]   = aS0[i];
                *(ull*)&rr[16 + i*4+2] = aS1[i];
            }
        }
        __syncthreads();

        /* ---- reduce + elementwise: all 256 threads, 4 cols each ---- */
        {
            int wr = ((row >> 2) << 3) + cf;
            int ib = (row & 3) * 4;
            float wc4[4] = {0.f, 0.f, 0.f, 0.f};
            float ws4[4] = {0.f, 0.f, 0.f, 0.f};
#pragma unroll
            for (int ksr = 0; ksr < 4; ksr++) {
                const float* r = &sR[(ksr*64 + wr)*SR_STRIDE];
                float4 c4 = *(const float4*)&r[ib];
                float4 s4 = *(const float4*)&r[16 + ib];
                wc4[0] += c4.x; wc4[1] += c4.y; wc4[2] += c4.z; wc4[3] += c4.w;
                ws4[0] += s4.x; ws4[1] += s4.y; ws4[2] += s4.z; ws4[3] += s4.w;
            }

            float4 fc = *(const float4*)&sC[so];
            float4 fs = *(const float4*)&sS[so];
            float ce[4] = {fc.x, fc.y, fc.z, fc.w};
            float se[4] = {fs.x, fs.y, fs.z, fs.w};
            float kv[4];
#pragma unroll
            for (int j = 0; j < 4; j++)
                kv[j] = fmaf(se[j], wc4[j] - cAnc, ce[j] * (sAnc - ws4[j]));

            float4 p0 = *(const float4*)&sP[so];
            float ph[4] = {p0.x, p0.y, p0.z, p0.w};
            float phiN[4];
            if (sub == 0) {
                *(float4*)&sA[so] = make_float4(kv[0], kv[1], kv[2], kv[3]);
#pragma unroll
                for (int j = 0; j < 4; j++) phiN[j] = fmaf(cNext, kv[j], ph[j]);
            } else if (sub == 3) {
                float4 a0 = *(const float4*)&sA[so];
                float av[4] = {a0.x, a0.y, a0.z, a0.w};
#pragma unroll
                for (int j = 0; j < 4; j++)
                    phiN[j] = fmaf(DT/6.0f, av[j] + kv[j], ph[j]);
                *(float4*)&sP[so] = make_float4(phiN[0], phiN[1], phiN[2], phiN[3]);
            } else {
                float4 a0 = *(const float4*)&sA[so];
                float av[4] = {a0.x, a0.y, a0.z, a0.w};
#pragma unroll
                for (int j = 0; j < 4; j++) av[j] = fmaf(2.0f, kv[j], av[j]);
                *(float4*)&sA[so] = make_float4(av[0], av[1], av[2], av[3]);
#pragma unroll
                for (int j = 0; j < 4; j++) phiN[j] = fmaf(cNext, kv[j], ph[j]);
            }

            if (e < NEV-1) {
                float cn[4], sn[4];
#pragma unroll
                for (int j = 0; j < 4; j++)
                    __sincosf(phiN[j], &sn[j], &cn[j]);
                *(float4*)&sC[so] = make_float4(cn[0], cn[1], cn[2], cn[3]);
                *(float4*)&sS[so] = make_float4(sn[0], sn[1], sn[2], sn[3]);
            }
        }

        if (e < NEV-1) {
            __syncthreads();
            m_tail(sC, sS, sXC, sXS, g_m[bufW], r0);
            /* ---- group barrier: 32 CTAs of this row group only ---- */
            __syncthreads();
            if (tid == 0) {
                __threadfence();
                atomicAdd(&g_cnt[grp*NEV + e], 1u);
                volatile unsigned* c = &g_cnt[grp*NEV + e];
                while (*c < (unsigned)GXS) { }
                __threadfence();
            }
            __syncthreads();
        }
    }

    /* ---- write back final phi for readout ---- */
    {
        float4 p = *(const float4*)&sP[so];
        *(float4*)&g_phi[gso] = p;
    }
}

/* ================= readout: [cos(phi), sin(phi)] @ Wout^T + b ===========
   2 batch rows per CTA (halves Wout L2 traffic); thread = 4 n-columns;
   warp shfl reduce, one smem pass, single barrier. */
__global__ void __launch_bounds__(256)
k_readout(const float* __restrict__ Wout,
          const float* __restrict__ bout,
          float* __restrict__ out) {
    __shared__ float red[8*2*COUT];
    int b0 = blockIdx.x*2, tid = threadIdx.x;
    int n4 = tid*4;

    float4 pa = *(const float4*)&g_phi[b0*NN + n4];
    float4 pb = *(const float4*)&g_phi[(b0+1)*NN + n4];
    float pha[4] = {pa.x, pa.y, pa.z, pa.w};
    float phb[4] = {pb.x, pb.y, pb.z, pb.w};
    float ca[4], sa[4], cb[4], sb[4];
#pragma unroll
    for (int j = 0; j < 4; j++) {
        sincosf(pha[j], &sa[j], &ca[j]);  /* accurate: feeds output */
        sincosf(phb[j], &sb[j], &cb[j]);
    }

    float acc[2][COUT];
#pragma unroll
    for (int cls = 0; cls < COUT; cls++) {
        float4 wcv = *(const float4*)&Wout[cls*(2*NN) + n4];
        float4 wsv = *(const float4*)&Wout[cls*(2*NN) + NN + n4];
        float a0 = ca[0]*wcv.x + sa[0]*wsv.x;
        a0 = fmaf(ca[1], wcv.y, a0); a0 = fmaf(sa[1], wsv.y, a0);
        a0 = fmaf(ca[2], wcv.z, a0); a0 = fmaf(sa[2], wsv.z, a0);
        a0 = fmaf(ca[3], wcv.w, a0); a0 = fmaf(sa[3], wsv.w, a0);
        acc[0][cls] = a0;
        float a1 = cb[0]*wcv.x + sb[0]*wsv.x;
        a1 = fmaf(cb[1], wcv.y, a1); a1 = fmaf(sb[1], wsv.y, a1);
        a1 = fmaf(cb[2], wcv.z, a1); a1 = fmaf(sb[2], wsv.z, a1);
        a1 = fmaf(cb[3], wcv.w, a1); a1 = fmaf(sb[3], wsv.w, a1);
        acc[1][cls] = a1;
    }
#pragma unroll
    for (int rr = 0; rr < 2; rr++)
#pragma unroll
        for (int cls = 0; cls < COUT; cls++)
#pragma unroll
            for (int w = 16; w > 0; w >>= 1)
                acc[rr][cls] += __shfl_xor_sync(0xffffffffu, acc[rr][cls], w);

    int warp = tid >> 5, lane = tid & 31;
    if (lane == 0)
#pragma unroll
        for (int rr = 0; rr < 2; rr++)
#pragma unroll
            for (int cls = 0; cls < COUT; cls++)
                red[warp*2*COUT + rr*COUT + cls] = acc[rr][cls];
    __syncthreads();

    if (tid < 2*COUT) {
        int rr = tid / COUT, cls = tid % COUT;
        float t = bout[cls];
#pragma unroll
        for (int w = 0; w < 8; w++) t += red[w*2*COUT + rr*COUT + cls];
        out[(b0+rr)*COUT + cls] = t;
    }
}

/* ================= host ================================================= */
extern "C" void kernel_launch(void* const* d_in, const int* in_sizes, int n_in,
                              void* d_out, int out_size) {
    (void)in_sizes; (void)n_in; (void)out_size;
    const float* x    = (const float*)d_in[0];
    const float* Wenc = (const float*)d_in[1];
    const float* benc = (const float*)d_in[2];
    const float* xi   = (const float*)d_in[3];
    const float* Wout = (const float*)d_in[4];
    const float* bout = (const float*)d_in[5];
    float* out = (float*)d_out;

    cudaFuncSetAttribute(k_encoder, cudaFuncAttributeMaxDynamicSharedMemorySize, SMEM_BYTES);
    cudaFuncSetAttribute(k_run,     cudaFuncAttributeMaxDynamicSharedMemorySize, SMEM_BYTES);

    EvalConsts ec;
    for (int e = 0; e < NEV; e++) {
        int step = e >> 2, sub = e & 3;
        float t0 = (float)step * DT;
        float tE = (sub == 0) ? t0 : ((sub == 3) ? t0 + DT : t0 + 0.5f*DT);
        float argf = OME * tE;
        double sa = sin((double)argf), ca = cos((double)argf);
        ec.sA[e] = (float)((double)A_ANC * sa);
        ec.cA[e] = (float)((double)A_ANC * ca);
        ec.cN[e] = (sub == 2) ? DT : 0.5f*DT;
    }

    k_init<<<512, 256>>>(xi);

    dim3 grid(GXS, NGRP);            /* 32 x 8 = 256 CTAs, all resident */
    k_encoder<<<grid, 256, SMEM_BYTES>>>(x, Wenc, benc);
    k_run<<<grid, 256, SMEM_BYTES>>>(ec);
    k_readout<<<BATCH/2, 256>>>(Wout, bout, out);
}

// round 12
// speedup vs baseline: 1.1428x; 1.1428x over previous
#include <cuda_runtime.h>
#include <math.h>

#define BATCH 256
#define NN    1024
#define PP    128
#define DIN   784
#define COUT  10
#define CH    32                     /* columns per CTA */
#define NEV   64                     /* RK4 evals */
#define NGRP  8                      /* row groups (blockIdx.y) */
#define GXS   32                     /* CTAs per group (blockIdx.x) */

#define TWO_PI_F 6.283185307179586f
#define DT       0.03125f            /* T/N_STEPS = 0.5/16, exact in fp32 */
#define BETA_N   (2.0f/1024.0f)
#define A_ANC    0.08f
#define OME      (TWO_PI_F*200.0f)

typedef unsigned long long ull;

__device__ __forceinline__ ull pack2(float a, float b) {
    ull r; asm("mov.b64 %0,{%1,%2};" : "=l"(r) : "f"(a), "f"(b)); return r;
}
__device__ __forceinline__ ull fma2(ull a, ull b, ull c) {
    ull d; asm("fma.rn.f32x2 %0,%1,%2,%3;" : "=l"(d) : "l"(a), "l"(b), "l"(c));
    return d;
}
__device__ __forceinline__ float hadd2(ull a) {
    float lo, hi;
    asm("mov.b64 {%0,%1},%2;" : "=f"(lo), "=f"(hi) : "l"(a));
    return lo + hi;
}
__device__ __forceinline__ unsigned su32(const void* p) {
    return (unsigned)__cvta_generic_to_shared(p);
}
#define CP16(dst, src) \
    asm volatile("cp.async.cg.shared.global [%0], [%1], 16;" :: "r"(dst), "l"(src))
#define CP_COMMIT() asm volatile("cp.async.commit_group;")
#define CP_WAIT(n)  asm volatile("cp.async.wait_group %0;" :: "n"(n))

struct EvalConsts { float sA[NEV]; float cA[NEV]; float cN[NEV]; };

/* ---- device scratch (static globals; no allocation allowed) ---- */
__device__ float g_xc[PP*NN];       /* cos(xi) [p][n] */
__device__ float g_xs[PP*NN];       /* sin(xi) [p][n] */
__device__ float g_phi[BATCH*NN];   /* base state */
__device__ float g_fc[BATCH*NN];    /* cos(phi_eval) features (encoder out) */
__device__ float g_fs[BATCH*NN];    /* sin(phi_eval) features */
__device__ float g_m[3][BATCH*PP];  /* rotating overlap buffers */
__device__ unsigned g_cnt[NGRP*NEV]; /* per-(group,eval) barrier counters */

/* ---- shared layout (floats) ---- */
#define SW_STRIDE 130                /* w tile [32][130] */
#define SX_STRIDE 36                 /* xc/xs tiles [128][36] */
#define SC_STRIDE 36                 /* c/s/phi/acc tiles [32][36] */
#define SR_STRIDE 36                 /* reduction: 256 writers x 36 */
#define SW_FLOATS (32*SW_STRIDE)     /* 4160 */
#define SX_FLOATS (128*SX_STRIDE)    /* 4608 */
#define SC_FLOATS (32*SC_STRIDE)     /* 1152 */
#define SR_FLOATS (256*SR_STRIDE)    /* 9216; first 4096 alias m-prefetch */
#define SMEM_FLOATS (SW_FLOATS + 2*SX_FLOATS + 4*SC_FLOATS + SR_FLOATS)
#define SMEM_BYTES  (SMEM_FLOATS*4)  /* 108800 bytes -> 2 CTAs/SM */

/* ================= init: cos/sin of xi, zero m bufs + barrier cnt ======= */
__global__ void k_init(const float* __restrict__ xi) {
    int i = blockIdx.x*256 + threadIdx.x;
    if (i < PP*NN) {
        float v = xi[i];
        g_xc[i] = cosf(v);
        g_xs[i] = sinf(v);
    }
    if (i < BATCH*PP) { g_m[0][i] = 0.f; g_m[1][i] = 0.f; }
    if (i < NGRP*NEV) g_cnt[i] = 0u;
}

/* load xc/xs tiles [128 p][32 n] for column chunk n0 (LDG path, encoder) */
__device__ __forceinline__ void load_xtiles(float* sXC, float* sXS, int n0) {
    for (int i = threadIdx.x; i < 128*8; i += 256) {
        int p = i >> 3, q = (i & 7) << 2;
        float4 a = *(const float4*)&g_xc[p*NN + n0 + q];
        *(float4*)&sXC[p*SX_STRIDE + q] = a;
        float4 b = *(const float4*)&g_xs[p*NN + n0 + q];
        *(float4*)&sXS[p*SX_STRIDE + q] = b;
    }
}

/* partial m over this CTA's 32-col chunk, atomicAdd into mbuf.
   fma2 version, register-light: 4 rows x 4 patterns per thread, full n.
   rb = warp id (row loads broadcast), pb = lane (pattern stride 144B,
   conflict-free per 8-lane phase). acc = 16 ull = 32 regs.               */
__device__ __forceinline__ void m_tail(const float* sC, const float* sS,
                                       const float* sXC, const float* sXS,
                                       float* mbuf, int r0) {
    int rb = threadIdx.x >> 5;       /* 0..7 -> rows rb*4..rb*4+3 */
    int pb = threadIdx.x & 31;       /* pats pb + 32*j            */
    ull acc[16];
#pragma unroll
    for (int i = 0; i < 16; i++) acc[i] = 0ull;
    const float* cB  = sC  + (rb*4)*SC_STRIDE;
    const float* sB  = sS  + (rb*4)*SC_STRIDE;
    const float* xcB = sXC + pb*SX_STRIDE;
    const float* xsB = sXS + pb*SX_STRIDE;
#pragma unroll
    for (int nn = 0; nn < CH; nn += 4) {
        ulonglong2 cr[4], sr[4];
#pragma unroll
        for (int r = 0; r < 4; r++) {
            cr[r] = *(const ulonglong2*)&cB[r*SC_STRIDE + nn];
            sr[r] = *(const ulonglong2*)&sB[r*SC_STRIDE + nn];
        }
#pragma unroll
        for (int j = 0; j < 4; j++) {
            ulonglong2 xc2 = *(const ulonglong2*)&xcB[j*32*SX_STRIDE + nn];
            ulonglong2 xs2 = *(const ulonglong2*)&xsB[j*32*SX_STRIDE + nn];
#pragma unroll
            for (int r = 0; r < 4; r++) {
                ull a = acc[j*4 + r];
                a = fma2(cr[r].x, xc2.x, a);
                a = fma2(cr[r].y, xc2.y, a);
                a = fma2(sr[r].x, xs2.x, a);
                a = fma2(sr[r].y, xs2.y, a);
                acc[j*4 + r] = a;
            }
        }
    }
#pragma unroll
    for (int j = 0; j < 4; j++)
#pragma unroll
        for (int r = 0; r < 4; r++)
            atomicAdd(&mbuf[(r0 + rb*4 + r)*PP + pb + 32*j],
                      hadd2(acc[j*4 + r]));
}

/* ================= encoder: phi0 = 2pi*sigmoid(x @ Wenc^T + b), + m0 ==== */
__global__ void __launch_bounds__(256, 2)
k_encoder(const float* __restrict__ x,
          const float* __restrict__ Wenc,
          const float* __restrict__ benc) {
    extern __shared__ float sm[];
    float* sA  = sm;                 /* [32][17] staging, aliases sW region */
    float* sB  = sm + 32*17;         /* [32][17] */
    float* sXC = sm + SW_FLOATS;
    float* sXS = sXC + SX_FLOATS;
    float* sC  = sXS + SX_FLOATS;
    float* sS  = sC + SC_FLOATS;

    int n0 = blockIdx.x*CH, r0 = blockIdx.y*32;
    int tid = threadIdx.x;
    int row = tid >> 3, ng = tid & 7, nb = ng*4;

    float acc[4];
#pragma unroll
    for (int i = 0; i < 4; i++) acc[i] = 0.f;

    for (int d0 = 0; d0 < DIN; d0 += 16) {
        for (int i = tid; i < 512; i += 256) {
            int r = i >> 4, j = i & 15;
            sA[r*17 + j] = x[(r0+r)*DIN + d0 + j];
            sB[r*17 + j] = Wenc[(n0+r)*DIN + d0 + j];
        }
        __syncthreads();
#pragma unroll
        for (int j = 0; j < 16; j++) {
            float xa = sA[row*17 + j];
#pragma unroll
            for (int i = 0; i < 4; i++) acc[i] += xa * sB[(nb+i)*17 + j];
        }
        __syncthreads();
    }

    load_xtiles(sXC, sXS, n0);

#pragma unroll
    for (int i = 0; i < 4; i++) {
        float z  = acc[i] + benc[n0 + nb + i];
        float p0 = TWO_PI_F / (1.0f + expf(-z));
        int gi = (r0+row)*NN + n0 + nb + i;
        g_phi[gi]  = p0;
        float ss, cc;
        __sincosf(p0, &ss, &cc);
        g_fc[gi] = cc;
        g_fs[gi] = ss;
        sC[row*SC_STRIDE + nb + i] = cc;
        sS[row*SC_STRIDE + nb + i] = ss;
    }
    __syncthreads();
    m_tail(sC, sS, sXC, sXS, g_m[0], r0);
}

/* ================= persistent RK4 kernel: all 64 evals =================== */
__global__ void __launch_bounds__(256, 2)
k_run(EvalConsts ec) {
    extern __shared__ float sm[];
    float* sW  = sm;
    float* sXC = sm + SW_FLOATS;
    float* sXS = sXC + SX_FLOATS;
    float* sC  = sXS + SX_FLOATS;      /* cos features of eval point */
    float* sS  = sC + SC_FLOATS;       /* sin features of eval point */
    float* sP  = sS + SC_FLOATS;       /* base phi                   */
    float* sA  = sP + SC_FLOATS;       /* RK4 accumulator            */
    float* sR  = sA + SC_FLOATS;       /* GEMM partials; [0,4096)=m  */

    int n0 = blockIdx.x*CH, r0 = blockIdx.y*32;
    int tid = threadIdx.x;
    int row = tid >> 3, cf = tid & 7;
    int so  = row*SC_STRIDE + cf*4;
    int gso = (r0+row)*NN + n0 + cf*4;
    int cta = blockIdx.y*GXS + blockIdx.x;
    int grp = blockIdx.y;

    /* ---- one-time loads: xi tiles + state ---- */
#pragma unroll
    for (int it = 0; it < 4; it++) {
        int i = tid + it*256;
        int p = i >> 3, q = (i & 7) << 2;
        CP16(su32(&sXC[p*SX_STRIDE + q]), &g_xc[p*NN + n0 + q]);
        CP16(su32(&sXS[p*SX_STRIDE + q]), &g_xs[p*NN + n0 + q]);
    }
    CP16(su32(&sC[so]), &g_fc[gso]);
    CP16(su32(&sS[so]), &g_fs[gso]);
    CP16(su32(&sP[so]), &g_phi[gso]);
    CP_COMMIT();

    for (int e = 0; e < NEV; e++) {
        int sub  = e & 3;
        int bufR = e % 3, bufW = (e + 1) % 3, bufZ = (e + 2) % 3;
        float sAnc = ec.sA[e], cAnc = ec.cA[e], cNext = ec.cN[e];

        /* prefetch m slice for this eval */
        {
            const float* gmp = &g_m[bufR][(r0+row)*PP + cf*16];
            unsigned d = su32(&sR[row*PP + cf*16]);
            CP16(d,      gmp);
            CP16(d + 16, gmp + 4);
            CP16(d + 32, gmp + 8);
            CP16(d + 48, gmp + 12);
        }
        CP_COMMIT();

        /* zero this group's slice of the buffer used two evals ahead */
        if (tid < 128) g_m[bufZ][cta*128 + tid] = 0.f;

        CP_WAIT(0);
        /* ---- softmax over 128 patterns (arg in [-2,2]: no max shift) ---- */
        {
            const float* mrow = &sR[row*PP + cf*16];
            float a[16];
            float ssum = 0.f;
#pragma unroll
            for (int j = 0; j < 16; j++) {
                a[j] = __expf(mrow[j] * BETA_N);
                ssum += a[j];
            }
#pragma unroll
            for (int w = 1; w < 8; w <<= 1)
                ssum += __shfl_xor_sync(0xffffffffu, ssum, w);
            float inv = 1.0f / ssum;
#pragma unroll
            for (int j = 0; j < 16; j++)
                sW[row*SW_STRIDE + cf*16 + j] = a[j] * inv;
        }
        __syncthreads();

        /* ---- coupling GEMM, tile 4 rows x 4 cols (f32x2), K-split 4 ---- */
        {
            int ks   = tid >> 6;
            int r6   = tid & 63;
            int rowg = r6 >> 3;
            int colg = r6 & 7;
            ull aC0[4], aC1[4], aS0[4], aS1[4];
#pragma unroll
            for (int i = 0; i < 4; i++) { aC0[i]=0ull; aC1[i]=0ull; aS0[i]=0ull; aS1[i]=0ull; }
            const float* wB  = &sW[(rowg*4)*SW_STRIDE + ks*32];
            const float* xcB = &sXC[(ks*32)*SX_STRIDE + colg*4];
            const float* xsB = &sXS[(ks*32)*SX_STRIDE + colg*4];
#pragma unroll 4
            for (int p = 0; p < 32; p++) {
                ulonglong2 cp = *(const ulonglong2*)&xcB[p*SX_STRIDE];
                ulonglong2 spv = *(const ulonglong2*)&xsB[p*SX_STRIDE];
#pragma unroll
                for (int i = 0; i < 4; i++) {
                    float wv = wB[i*SW_STRIDE + p];
                    ull wp = pack2(wv, wv);
                    aC0[i] = fma2(wp, cp.x,  aC0[i]);
                    aC1[i] = fma2(wp, cp.y,  aC1[i]);
                    aS0[i] = fma2(wp, spv.x, aS0[i]);
                    aS1[i] = fma2(wp, spv.y, aS1[i]);
                }
            }
            float* rr = &sR[tid*SR_STRIDE];
#pragma unroll
            for (int i = 0; i < 4; i++) {
                *(ull*)&rr[i*4]        = aC0[i];
                *(ull*)&rr[i*4 + 2]    = aC1[i];
                *(ull*)&rr[16 + i*4]   = aS0[i];
                *(ull*)&rr[16 + i*4+2] = aS1[i];
            }
        }
        __syncthreads();

        /* ---- reduce + elementwise: all 256 threads, 4 cols each ---- */
        {
            int wr = ((row >> 2) << 3) + cf;
            int ib = (row & 3) * 4;
            float wc4[4] = {0.f, 0.f, 0.f, 0.f};
            float ws4[4] = {0.f, 0.f, 0.f, 0.f};
#pragma unroll
            for (int ksr = 0; ksr < 4; ksr++) {
                const float* r = &sR[(ksr*64 + wr)*SR_STRIDE];
                float4 c4 = *(const float4*)&r[ib];
                float4 s4 = *(const float4*)&r[16 + ib];
                wc4[0] += c4.x; wc4[1] += c4.y; wc4[2] += c4.z; wc4[3] += c4.w;
                ws4[0] += s4.x; ws4[1] += s4.y; ws4[2] += s4.z; ws4[3] += s4.w;
            }

            float4 fc = *(const float4*)&sC[so];
            float4 fs = *(const float4*)&sS[so];
            float ce[4] = {fc.x, fc.y, fc.z, fc.w};
            float se[4] = {fs.x, fs.y, fs.z, fs.w};
            float kv[4];
#pragma unroll
            for (int j = 0; j < 4; j++)
                kv[j] = fmaf(se[j], wc4[j] - cAnc, ce[j] * (sAnc - ws4[j]));

            float4 p0 = *(const float4*)&sP[so];
            float ph[4] = {p0.x, p0.y, p0.z, p0.w};
            float phiN[4];
            if (sub == 0) {
                *(float4*)&sA[so] = make_float4(kv[0], kv[1], kv[2], kv[3]);
#pragma unroll
                for (int j = 0; j < 4; j++) phiN[j] = fmaf(cNext, kv[j], ph[j]);
            } else if (sub == 3) {
                float4 a0 = *(const float4*)&sA[so];
                float av[4] = {a0.x, a0.y, a0.z, a0.w};
#pragma unroll
                for (int j = 0; j < 4; j++)
                    phiN[j] = fmaf(DT/6.0f, av[j] + kv[j], ph[j]);
                *(float4*)&sP[so] = make_float4(phiN[0], phiN[1], phiN[2], phiN[3]);
            } else {
                float4 a0 = *(const float4*)&sA[so];
                float av[4] = {a0.x, a0.y, a0.z, a0.w};
#pragma unroll
                for (int j = 0; j < 4; j++) av[j] = fmaf(2.0f, kv[j], av[j]);
                *(float4*)&sA[so] = make_float4(av[0], av[1], av[2], av[3]);
#pragma unroll
                for (int j = 0; j < 4; j++) phiN[j] = fmaf(cNext, kv[j], ph[j]);
            }

            if (e < NEV-1) {
                float cn[4], sn[4];
#pragma unroll
                for (int j = 0; j < 4; j++)
                    __sincosf(phiN[j], &sn[j], &cn[j]);
                *(float4*)&sC[so] = make_float4(cn[0], cn[1], cn[2], cn[3]);
                *(float4*)&sS[so] = make_float4(sn[0], sn[1], sn[2], sn[3]);
            }
        }

        if (e < NEV-1) {
            __syncthreads();
            m_tail(sC, sS, sXC, sXS, g_m[bufW], r0);
            /* ---- group barrier: 32 CTAs of this row group only ---- */
            __syncthreads();
            if (tid == 0) {
                __threadfence();
                atomicAdd(&g_cnt[grp*NEV + e], 1u);
                volatile unsigned* c = &g_cnt[grp*NEV + e];
                while (*c < (unsigned)GXS) { }
                __threadfence();
            }
            __syncthreads();
        }
    }

    /* ---- write back final phi for readout ---- */
    {
        float4 p = *(const float4*)&sP[so];
        *(float4*)&g_phi[gso] = p;
    }
}

/* ================= readout: [cos(phi), sin(phi)] @ Wout^T + b ===========
   2 batch rows per CTA; thread = 4 n-columns; warp shfl reduce, one smem
   pass, single barrier. */
__global__ void __launch_bounds__(256)
k_readout(const float* __restrict__ Wout,
          const float* __restrict__ bout,
          float* __restrict__ out) {
    __shared__ float red[8*2*COUT];
    int b0 = blockIdx.x*2, tid = threadIdx.x;
    int n4 = tid*4;

    float4 pa = *(const float4*)&g_phi[b0*NN + n4];
    float4 pb = *(const float4*)&g_phi[(b0+1)*NN + n4];
    float pha[4] = {pa.x, pa.y, pa.z, pa.w};
    float phb[4] = {pb.x, pb.y, pb.z, pb.w};
    float ca[4], sa[4], cb[4], sb[4];
#pragma unroll
    for (int j = 0; j < 4; j++) {
        sincosf(pha[j], &sa[j], &ca[j]);  /* accurate: feeds output */
        sincosf(phb[j], &sb[j], &cb[j]);
    }

    float acc[2][COUT];
#pragma unroll
    for (int cls = 0; cls < COUT; cls++) {
        float4 wcv = *(const float4*)&Wout[cls*(2*NN) + n4];
        float4 wsv = *(const float4*)&Wout[cls*(2*NN) + NN + n4];
        float a0 = ca[0]*wcv.x + sa[0]*wsv.x;
        a0 = fmaf(ca[1], wcv.y, a0); a0 = fmaf(sa[1], wsv.y, a0);
        a0 = fmaf(ca[2], wcv.z, a0); a0 = fmaf(sa[2], wsv.z, a0);
        a0 = fmaf(ca[3], wcv.w, a0); a0 = fmaf(sa[3], wsv.w, a0);
        acc[0][cls] = a0;
        float a1 = cb[0]*wcv.x + sb[0]*wsv.x;
        a1 = fmaf(cb[1], wcv.y, a1); a1 = fmaf(sb[1], wsv.y, a1);
        a1 = fmaf(cb[2], wcv.z, a1); a1 = fmaf(sb[2], wsv.z, a1);
        a1 = fmaf(cb[3], wcv.w, a1); a1 = fmaf(sb[3], wsv.w, a1);
        acc[1][cls] = a1;
    }
#pragma unroll
    for (int rr = 0; rr < 2; rr++)
#pragma unroll
        for (int cls = 0; cls < COUT; cls++)
#pragma unroll
            for (int w = 16; w > 0; w >>= 1)
                acc[rr][cls] += __shfl_xor_sync(0xffffffffu, acc[rr][cls], w);

    int warp = tid >> 5, lane = tid & 31;
    if (lane == 0)
#pragma unroll
        for (int rr = 0; rr < 2; rr++)
#pragma unroll
            for (int cls = 0; cls < COUT; cls++)
                red[warp*2*COUT + rr*COUT + cls] = acc[rr][cls];
    __syncthreads();

    if (tid < 2*COUT) {
        int rr = tid / COUT, cls = tid % COUT;
        float t = bout[cls];
#pragma unroll
        for (int w = 0; w < 8; w++) t += red[w*2*COUT + rr*COUT + cls];
        out[(b0+rr)*COUT + cls] = t;
    }
}

/* ================= host ================================================= */
extern "C" void kernel_launch(void* const* d_in, const int* in_sizes, int n_in,
                              void* d_out, int out_size) {
    (void)in_sizes; (void)n_in; (void)out_size;
    const float* x    = (const float*)d_in[0];
    const float* Wenc = (const float*)d_in[1];
    const float* benc = (const float*)d_in[2];
    const float* xi   = (const float*)d_in[3];
    const float* Wout = (const float*)d_in[4];
    const float* bout = (const float*)d_in[5];
    float* out = (float*)d_out;

    cudaFuncSetAttribute(k_encoder, cudaFuncAttributeMaxDynamicSharedMemorySize, SMEM_BYTES);
    cudaFuncSetAttribute(k_run,     cudaFuncAttributeMaxDynamicSharedMemorySize, SMEM_BYTES);

    EvalConsts ec;
    for (int e = 0; e < NEV; e++) {
        int step = e >> 2, sub = e & 3;
        float t0 = (float)step * DT;
        float tE = (sub == 0) ? t0 : ((sub == 3) ? t0 + DT : t0 + 0.5f*DT);
        float argf = OME * tE;
        double sa = sin((double)argf), ca = cos((double)argf);
        ec.sA[e] = (float)((double)A_ANC * sa);
        ec.cA[e] = (float)((double)A_ANC * ca);
        ec.cN[e] = (sub == 2) ? DT : 0.5f*DT;
    }

    k_init<<<512, 256>>>(xi);

    dim3 grid(GXS, NGRP);            /* 32 x 8 = 256 CTAs, all resident */
    k_encoder<<<grid, 256, SMEM_BYTES>>>(x, Wenc, benc);
    k_run<<<grid, 256, SMEM_BYTES>>>(ec);
    k_readout<<<BATCH/2, 256>>>(Wout, bout, out);
}